// round 9
// baseline (speedup 1.0000x reference)
#include <cuda_runtime.h>
#include <cstdint>

#define Hc   256
#define Bc   64
#define Tc   256
#define Ec   300
#define NB   128          // 2 batch groups x 64 CTAs
#define NT   512          // 16 warps/CTA
typedef unsigned long long ull;

// ---------------- device scratch (no allocations allowed) ----------------
__device__ float g_pre0[(size_t)Tc * 1024 * Bc];   // [t][gatecol][b]  (64 MB)
__device__ float g_h0[4][2 * Hc * 32];             // layer0 h, ring-4, [grp][unit][32b]
__device__ float g_h1[2][2 * Hc * 32];             // layer1 h, ring-2
__device__ unsigned g_flags[NB * 8];               // 32B-padded per-CTA epoch flags
__device__ unsigned g_gen2[2 * 8];                 // per-group generation words
__device__ int g_is64;

// ---------------- helpers ----------------
__device__ __forceinline__ void fma2(ull& d, ull a, ull b) {
    asm("fma.rn.f32x2 %0, %1, %2, %0;" : "+l"(d) : "l"(a), "l"(b));
}
__device__ __forceinline__ ull dup2(float x) {
    ull r;
    asm("mov.b64 %0, {%1, %1};" : "=l"(r) : "f"(x));
    return r;
}
__device__ __forceinline__ float2 unpk(ull v) {
    float2 r;
    asm("mov.b64 {%0, %1}, %2;" : "=f"(r.x), "=f"(r.y) : "l"(v));
    return r;
}
__device__ __forceinline__ float sigf(float x)  { return 1.0f / (1.0f + __expf(-x)); }
__device__ __forceinline__ float tanhf_(float x){ return 2.0f / (1.0f + __expf(-2.0f * x)) - 1.0f; }

__device__ __forceinline__ void st_rel(unsigned* p, unsigned v) {
    asm volatile("st.release.gpu.global.u32 [%0], %1;" :: "l"(p), "r"(v) : "memory");
}
__device__ __forceinline__ unsigned ld_acq(const unsigned* p) {
    unsigned v;
    asm volatile("ld.acquire.gpu.global.u32 %0, [%1];" : "=r"(v) : "l"(p) : "memory");
    return v;
}

// ---------------- kernel: int32 vs int64 token detector ----------------
__global__ void k_detect(const int* __restrict__ x) {
    int v = 0;
    for (int i = threadIdx.x * 2 + 1; i < Bc * Tc; i += 1024) v |= x[i];
    int any = __syncthreads_or(v);
    if (threadIdx.x == 0) g_is64 = (any == 0) ? 1 : 0;
}

// ---------------- kernel: pre0[t][c][b] = b0[c] + emb[x[b,t]] . W0x[:,c] ----------------
__global__ void __launch_bounds__(256) k_pre(const int* __restrict__ x,
                                             const float* __restrict__ emb,
                                             const float* __restrict__ W0,
                                             const float* __restrict__ b0) {
    extern __shared__ float semb[];  // [Ec][66]
    const int t = blockIdx.y, ct = blockIdx.x;
    const int tid = threadIdx.x, lane = tid & 31, w = tid >> 5;
    const int is64 = g_is64;

    for (int bb = w; bb < Bc; bb += 8) {
        int idx = bb * Tc + t;
        int tok = is64 ? x[2 * idx] : x[idx];
        const float* er = emb + (size_t)tok * Ec;
        for (int e = lane; e < Ec; e += 32) semb[e * 66 + bb] = er[e];
    }
    __syncthreads();

    const int cg = tid & 63, bg = tid >> 6;
    const int c0 = ct * 256 + cg * 4;

    ull a0[8], a1[8], a2[8], a3[8];
#pragma unroll
    for (int j = 0; j < 8; j++) { a0[j] = 0ull; a1[j] = 0ull; a2[j] = 0ull; a3[j] = 0ull; }

#pragma unroll 4
    for (int e = 0; e < Ec; e++) {
        float4 wv = __ldg((const float4*)(W0 + (size_t)e * 1024 + c0));
        ull w0 = dup2(wv.x), w1 = dup2(wv.y), w2 = dup2(wv.z), w3 = dup2(wv.w);
        const ull* sp = (const ull*)(semb + e * 66 + bg * 16);
        ull p0 = sp[0], p1 = sp[1], p2 = sp[2], p3 = sp[3];
        ull p4 = sp[4], p5 = sp[5], p6 = sp[6], p7 = sp[7];
        fma2(a0[0], p0, w0); fma2(a0[1], p1, w0); fma2(a0[2], p2, w0); fma2(a0[3], p3, w0);
        fma2(a0[4], p4, w0); fma2(a0[5], p5, w0); fma2(a0[6], p6, w0); fma2(a0[7], p7, w0);
        fma2(a1[0], p0, w1); fma2(a1[1], p1, w1); fma2(a1[2], p2, w1); fma2(a1[3], p3, w1);
        fma2(a1[4], p4, w1); fma2(a1[5], p5, w1); fma2(a1[6], p6, w1); fma2(a1[7], p7, w1);
        fma2(a2[0], p0, w2); fma2(a2[1], p1, w2); fma2(a2[2], p2, w2); fma2(a2[3], p3, w2);
        fma2(a2[4], p4, w2); fma2(a2[5], p5, w2); fma2(a2[6], p6, w2); fma2(a2[7], p7, w2);
        fma2(a3[0], p0, w3); fma2(a3[1], p1, w3); fma2(a3[2], p2, w3); fma2(a3[3], p3, w3);
        fma2(a3[4], p4, w3); fma2(a3[5], p5, w3); fma2(a3[6], p6, w3); fma2(a3[7], p7, w3);
    }

    float4 bb4 = __ldg((const float4*)(b0 + c0));
    float bs[4] = {bb4.x, bb4.y, bb4.z, bb4.w};
    ull* accs[4] = {a0, a1, a2, a3};
#pragma unroll
    for (int j = 0; j < 4; j++) {
        float* op = g_pre0 + ((size_t)t * 1024 + c0 + j) * Bc + bg * 16;
#pragma unroll
        for (int p = 0; p < 8; p++) {
            float2 v = unpk(accs[j][p]);
            v.x += bs[j]; v.y += bs[j];
            *(float2*)(op + 2 * p) = v;
        }
    }
}

// ---------------- kernel: persistent barrier-overlapped recurrence ----------------
// 2 groups x 64 CTAs; CTA owns 4 units x 32 batches of both layers.
// Layer1 lags layer0 by TWO supersteps. Per superstep s (0..257):
//   ph1 arrive(epoch s+2)                       [covers last step's h stores]
//   ph2 B1: W1x pass on h0[s-2]   (pre-wait — overlaps barrier round-trip+skew)
//   ph3 wait(gen == s+2)
//   ph4 A: W0h on h0[s-1];  B2: W1h on h1[s-3]  (post-wait)
//   ph5 sync; ph6 reduce+activate+store h0[s] / h1[s-2]; ph7 sync
__global__ void __launch_bounds__(512) k_rnn(const float* __restrict__ W0,
                                             const float* __restrict__ W1,
                                             const float* __restrict__ b1,
                                             float* __restrict__ out) {
    extern __shared__ char sm[];
    ull*   swA  = (ull*)sm;                    // W0h col-pairs [k][8]   16KB
    ull*   swX  = swA + 256 * 8;               // W1x col-pairs [k][8]   16KB
    ull*   swH  = swX + 256 * 8;               // W1h col-pairs [k][8]   16KB
    ull*   ggA  = swH + 256 * 8;               // layer0 partials [8][16][32]  32KB
    ull*   ggB  = ggA + 8 * 16 * 32;           // layer1 partials [8][32][32]  64KB
    float* b1sh = (float*)(ggB + 8 * 32 * 32);

    const int tid = threadIdx.x, lane = tid & 31, w = tid >> 5, bid = blockIdx.x;
    const int ub = bid & 63, gr = bid >> 6;
    const int goff = gr * (Hc * 32);

    // stage weights as float2 col-pairs (pair pc -> local cols 2pc,2pc+1;
    // local col c: gate g=c>>2, unit u=c&3, global G = g*256 + ub*4 + u)
    for (int idx = tid; idx < 256 * 8; idx += NT) {
        int k = idx >> 3, pc = idx & 7;
        int c0 = pc * 2, G = (c0 >> 2) * 256 + ub * 4 + (c0 & 3);
        swA[k * 8 + pc] = *(const ull*)(W0 + (size_t)(Ec + k) * 1024 + G);
        swX[k * 8 + pc] = *(const ull*)(W1 + (size_t)k * 1024 + G);
        swH[k * 8 + pc] = *(const ull*)(W1 + (size_t)(Hc + k) * 1024 + G);
    }
    if (tid < 16) {
        int c = tid, G = (c >> 2) * 256 + ub * 4 + (c & 3);
        b1sh[c] = __ldg(b1 + G);
    }
    // zero this CTA's h slots in all ring buffers
    if (tid < 256) {
        int l = tid >> 7, u = (tid >> 5) & 3, b = tid & 31;
        int off = goff + (ub * 4 + u) * 32 + b;
        if (l == 0) { g_h0[0][off] = 0.f; g_h0[1][off] = 0.f; g_h0[2][off] = 0.f; g_h0[3][off] = 0.f; }
        else        { g_h1[0][off] = 0.f; g_h1[1][off] = 0.f; }
    }
    float creg = 0.f;
    // init barrier (epoch 1)
    __syncthreads();
    if (tid == 0) st_rel(&g_flags[bid * 8], 1u);
    if (ub == 0 && tid < 32) {
        const int base = gr * 64;
        bool ok;
        do {
            unsigned v0 = ld_acq(&g_flags[(base + tid) * 8]);
            unsigned v1 = ld_acq(&g_flags[(base + 32 + tid) * 8]);
            ok = (v0 >= 1u) & (v1 >= 1u);
        } while (!__all_sync(0xffffffffu, ok));
        if (tid == 0) st_rel(&g_gen2[gr * 8], 1u);
    } else if (tid == 0) {
        while (ld_acq(&g_gen2[gr * 8]) < 1u) {}
    }
    __syncthreads();

    const int l_ = tid >> 7, u_ = (tid >> 5) & 3, b_ = tid & 31;   // reducers: tid<256
    const int U_ = ub * 4 + u_;

    for (int s = 0; s <= Tc + 1; s++) {
        const unsigned epoch = (unsigned)(s + 2);
        // ---- ph1: arrive (covers all previous-step stores) ----
        if (tid == 0) st_rel(&g_flags[bid * 8], epoch);

        // ---- ph2: B1 = W1x pass on h0[s-2] (barrier-stale safe) ----
        float pf[4] = {0.f, 0.f, 0.f, 0.f};
        if (tid < 128 && s <= Tc - 1) {
#pragma unroll
            for (int g = 0; g < 4; g++)
                pf[g] = __ldg(g_pre0 + ((size_t)s * 1024 + g * 256 + U_) * Bc + gr * 32 + b_);
        }
        if (s >= 2) {
            const float* hp = g_h0[(s - 2) & 3] + goff + (w * 16) * 32 + lane;
            float hv[16];
#pragma unroll
            for (int kk = 0; kk < 16; kk++) hv[kk] = __ldcg(hp + kk * 32);
            ull aX[8];
#pragma unroll
            for (int j = 0; j < 8; j++) aX[j] = 0ull;
#pragma unroll
            for (int kk = 0; kk < 16; kk++) {
                ull h2 = dup2(hv[kk]);
                const ulonglong2* qp = (const ulonglong2*)(swX + (size_t)(w * 16 + kk) * 8);
                ulonglong2 q0 = qp[0], q1 = qp[1], q2 = qp[2], q3 = qp[3];
                fma2(aX[0], h2, q0.x); fma2(aX[1], h2, q0.y);
                fma2(aX[2], h2, q1.x); fma2(aX[3], h2, q1.y);
                fma2(aX[4], h2, q2.x); fma2(aX[5], h2, q2.y);
                fma2(aX[6], h2, q3.x); fma2(aX[7], h2, q3.y);
            }
#pragma unroll
            for (int pc = 0; pc < 8; pc++)
                ggB[(pc * 32 + w) * 32 + lane] = aX[pc];
        }

        // ---- ph3: wait for epoch ----
        if (ub == 0 && tid < 32) {
            const int base = gr * 64;
            bool ok;
            do {
                unsigned v0 = ld_acq(&g_flags[(base + tid) * 8]);
                unsigned v1 = ld_acq(&g_flags[(base + 32 + tid) * 8]);
                ok = (v0 >= epoch) & (v1 >= epoch);
            } while (!__all_sync(0xffffffffu, ok));
            if (tid == 0) st_rel(&g_gen2[gr * 8], epoch);
        } else if (tid == 0) {
            while (ld_acq(&g_gen2[gr * 8]) < epoch) {}
        }
        __syncthreads();

        // ---- ph4: A = W0h on h0[s-1]; B2 = W1h on h1[s-3] ----
        const bool doA = (s <= Tc - 1), doB = (s >= 2);
        float hv0[16], hv1[16];
        if (doA) {
            const float* hp = g_h0[(s - 1) & 3] + goff + (w * 16) * 32 + lane;
#pragma unroll
            for (int kk = 0; kk < 16; kk++) hv0[kk] = __ldcg(hp + kk * 32);
        }
        if (doB) {
            const float* hp = g_h1[(s - 3) & 1] + goff + (w * 16) * 32 + lane;
#pragma unroll
            for (int kk = 0; kk < 16; kk++) hv1[kk] = __ldcg(hp + kk * 32);
        }
        if (doA) {
            ull aA[8];
#pragma unroll
            for (int j = 0; j < 8; j++) aA[j] = 0ull;
#pragma unroll
            for (int kk = 0; kk < 16; kk++) {
                ull h2 = dup2(hv0[kk]);
                const ulonglong2* qp = (const ulonglong2*)(swA + (size_t)(w * 16 + kk) * 8);
                ulonglong2 q0 = qp[0], q1 = qp[1], q2 = qp[2], q3 = qp[3];
                fma2(aA[0], h2, q0.x); fma2(aA[1], h2, q0.y);
                fma2(aA[2], h2, q1.x); fma2(aA[3], h2, q1.y);
                fma2(aA[4], h2, q2.x); fma2(aA[5], h2, q2.y);
                fma2(aA[6], h2, q3.x); fma2(aA[7], h2, q3.y);
            }
#pragma unroll
            for (int pc = 0; pc < 8; pc++)
                ggA[(pc * 16 + w) * 32 + lane] = aA[pc];
        }
        if (doB) {
            ull aH[8];
#pragma unroll
            for (int j = 0; j < 8; j++) aH[j] = 0ull;
#pragma unroll
            for (int kk = 0; kk < 16; kk++) {
                ull h2 = dup2(hv1[kk]);
                const ulonglong2* qp = (const ulonglong2*)(swH + (size_t)(w * 16 + kk) * 8);
                ulonglong2 q0 = qp[0], q1 = qp[1], q2 = qp[2], q3 = qp[3];
                fma2(aH[0], h2, q0.x); fma2(aH[1], h2, q0.y);
                fma2(aH[2], h2, q1.x); fma2(aH[3], h2, q1.y);
                fma2(aH[4], h2, q2.x); fma2(aH[5], h2, q2.y);
                fma2(aH[6], h2, q3.x); fma2(aH[7], h2, q3.y);
            }
#pragma unroll
            for (int pc = 0; pc < 8; pc++)
                ggB[(pc * 32 + 16 + w) * 32 + lane] = aH[pc];
        }
        __syncthreads();   // ph5

        // ---- ph6: reduce + activate + store ----
        const bool active = (tid < 256) && ((l_ == 0) ? doA : doB);
        if (active) {
            float gate[4];
#pragma unroll
            for (int g = 0; g < 4; g++) {
                int c = g * 4 + u_, pc = c >> 1, par = c & 1;
                float sum = 0.f;
                if (l_ == 0) {
                    const float* pp = (const float*)ggA + ((pc * 16) * 32 + b_) * 2 + par;
#pragma unroll
                    for (int ww = 0; ww < 16; ww++) sum += pp[ww * 64];
                    gate[g] = sum + pf[g];
                } else {
                    const float* pp = (const float*)ggB + ((pc * 32) * 32 + b_) * 2 + par;
#pragma unroll
                    for (int ww = 0; ww < 32; ww++) sum += pp[ww * 64];
                    gate[g] = sum + b1sh[c];
                }
            }
            float ii = sigf(gate[0]);
            float jj = tanhf_(gate[1]);
            float ff = sigf(gate[2] + 1.0f);       // FORGET_BIAS
            float oo = sigf(gate[3]);
            creg = creg * ff + ii * jj;
            float h = tanhf_(creg) * oo;
            int off = goff + U_ * 32 + b_;
            if (l_ == 0) {
                g_h0[s & 3][off] = h;              // h0[s]
            } else if (s < Tc + 1) {
                g_h1[s & 1][off] = h;              // h1[s-2]
            } else {
                out[(gr * 32 + b_) * Hc + U_] = h; // h1[T-1] -> output
            }
        }
        __syncthreads();   // ph7: protect ggB vs next step's ph2 STS
    }
}

// ---------------- kernel: reset barrier state (runs BEFORE k_rnn in-stream) ----------------
__global__ void k_reset() {
    int i = blockIdx.x * blockDim.x + threadIdx.x;
    if (i < NB * 8) g_flags[i] = 0u;
    if (i < 2 * 8) g_gen2[i] = 0u;
}

// ---------------- host launcher ----------------
extern "C" void kernel_launch(void* const* d_in, const int* in_sizes, int n_in,
                              void* d_out, int out_size) {
    const int*   x   = (const int*)d_in[0];
    const float* emb = (const float*)d_in[1];
    const float* W0  = (const float*)d_in[2];
    const float* b0  = (const float*)d_in[3];
    const float* W1  = (const float*)d_in[4];
    const float* b1  = (const float*)d_in[5];
    float*       out = (float*)d_out;
    (void)in_sizes; (void)n_in; (void)out_size;

    const int smem_pre = Ec * 66 * 4;                                   // 79200 B
    const int smem_rnn = 3 * 256 * 8 * 8 + 8 * 16 * 32 * 8 + 8 * 32 * 32 * 8 + 64;  // 147520 B

    static bool attr_done = false;
    if (!attr_done) {
        cudaFuncSetAttribute(k_pre, cudaFuncAttributeMaxDynamicSharedMemorySize, smem_pre);
        cudaFuncSetAttribute(k_rnn, cudaFuncAttributeMaxDynamicSharedMemorySize, smem_rnn);
        attr_done = true;
    }

    // order kept so the profiler lands on k_rnn
    k_detect<<<1, 512>>>(x);
    k_pre<<<dim3(4, 256), 256, smem_pre>>>(x, emb, W0, b0);
    k_reset<<<4, 256>>>();
    k_rnn<<<NB, NT, smem_rnn>>>(W0, W1, b1, out);
}